// round 1
// baseline (speedup 1.0000x reference)
#include <cuda_runtime.h>
#include <math.h>

// Problem constants
#define BATCH 16
#define IMH 768
#define IMW 768
#define TILE 32
#define R3 9                 // gaussian sigma=3 -> k=19, radius 9
#define R1 3                 // gaussian sigma=1 -> k=7, radius 3
#define LOAD (TILE + 2*R3)   // 50
#define RSTR (LOAD + 2)      // 52, padded row stride for raw tiles
#define H3STR (TILE + 1)     // 33, stride for blurred buffers
#define H1ROWS (TILE + 2*R1) // 38
#define NBINS 2048
#define NTHREADS 256
#define NACC 15

// dynamic smem layout (floats):
//  s_xi  : LOAD*RSTR        (2600)
//  s_yp  : LOAD*RSTR        (2600)
//  s_xm  : LOAD*RSTR        (2600)  -- reused as h1 buffers (2*38*33 = 2508) after G3 h-pass
//  s_h3  : 3*LOAD*H3STR     (4950)
//  s_hist: 2*NBINS uint     (4096 words)
#define SMEM_FLOATS (3*LOAD*RSTR + 3*LOAD*H3STR)
#define SMEM_BYTES  (SMEM_FLOATS*4 + 2*NBINS*4)

__device__ double       g_acc[NACC];
__device__ unsigned int g_hist[2*NBINS];

__global__ void zero_kernel() {
    int t = blockIdx.x * blockDim.x + threadIdx.x;
    if (t < NACC) g_acc[t] = 0.0;
    for (int i = t; i < 2*NBINS; i += gridDim.x * blockDim.x) g_hist[i] = 0u;
}

__global__ __launch_bounds__(NTHREADS)
void main_kernel(const float* __restrict__ yp_g,
                 const float* __restrict__ np_g,
                 const float* __restrict__ xi_g,
                 const float* __restrict__ xm_g,
                 const float* __restrict__ wt_g,
                 const float* __restrict__ ns_g)
{
    extern __shared__ float smem[];
    float* s_xi = smem;
    float* s_yp = s_xi + LOAD*RSTR;
    float* s_xm = s_yp + LOAD*RSTR;      // later aliased as h1 buffers
    float* s_h3 = s_xm + LOAD*RSTR;
    unsigned int* s_hist = (unsigned int*)(s_h3 + 3*LOAD*H3STR);

    __shared__ float s_g3[19];
    __shared__ float s_g1[7];
    __shared__ float s_part[NACC][8];

    const int tid = threadIdx.x;

    // Gaussian weights (computed once per block; matches normalized exp form)
    if (tid == 0) {
        float s = 0.f;
        for (int i = 0; i < 19; i++) {
            float c = (float)(i - 9) / 3.0f;
            float v = expf(-0.5f * c * c);
            s_g3[i] = v; s += v;
        }
        for (int i = 0; i < 19; i++) s_g3[i] /= s;
        s = 0.f;
        for (int i = 0; i < 7; i++) {
            float c = (float)(i - 3) / 1.0f;
            float v = expf(-0.5f * c * c);
            s_g1[i] = v; s += v;
        }
        for (int i = 0; i < 7; i++) s_g1[i] /= s;
    }
    for (int i = tid; i < 2*NBINS; i += NTHREADS) s_hist[i] = 0u;

    const int oy = blockIdx.y * TILE;
    const int ox = blockIdx.x * TILE;
    const int img = blockIdx.z * (IMH * IMW);

    // ---- load raw tiles with halo (zero pad outside image) ----
    for (int i = tid; i < LOAD*LOAD; i += NTHREADS) {
        int r = i / LOAD, c = i % LOAD;
        int gy = oy + r - R3, gx = ox + c - R3;
        bool in = (gy >= 0) & (gy < IMH) & (gx >= 0) & (gx < IMW);
        float vx = 0.f, vy = 0.f, vm = 0.f;
        if (in) {
            int g = img + gy * IMW + gx;
            vx = xi_g[g]; vy = yp_g[g]; vm = xm_g[g];
        }
        s_xi[r*RSTR + c] = vx;
        s_yp[r*RSTR + c] = vy;
        s_xm[r*RSTR + c] = vm;
    }
    __syncthreads();

    // ---- horizontal G3 pass: all 50 rows x 32 center cols, 3 arrays ----
    for (int i = tid; i < LOAD*TILE; i += NTHREADS) {
        int r = i / TILE, c = i % TILE;
        float a = 0.f, b = 0.f, m = 0.f;
        int base = r*RSTR + c;
        #pragma unroll
        for (int t = 0; t < 19; t++) {
            float w = s_g3[t];
            a += w * s_xi[base + t];
            b += w * s_yp[base + t];
            m += w * s_xm[base + t];
        }
        s_h3[0*LOAD*H3STR + r*H3STR + c] = a;
        s_h3[1*LOAD*H3STR + r*H3STR + c] = b;
        s_h3[2*LOAD*H3STR + r*H3STR + c] = m;
    }
    __syncthreads();

    // ---- horizontal G1 pass into aliased s_xm (x_mid raw no longer needed) ----
    float* s_h1 = s_xm;
    for (int i = tid; i < H1ROWS*TILE; i += NTHREADS) {
        int r = i / TILE, c = i % TILE;   // h1 row r == raw row r+6
        float a = 0.f, b = 0.f;
        int base = (r + 6)*RSTR + c + 6;
        #pragma unroll
        for (int t = 0; t < 7; t++) {
            float w = s_g1[t];
            a += w * s_xi[base + t];
            b += w * s_yp[base + t];
        }
        s_h1[0*H1ROWS*H3STR + r*H3STR + c] = a;
        s_h1[1*H1ROWS*H3STR + r*H3STR + c] = b;
    }
    __syncthreads();

    // ---- per output pixel ----
    float p_rc = 0.f, p_nb = 0.f, p_sxi = 0.f, p_syp = 0.f;
    float p_ex = 0.f, p_ey = 0.f, p_ntex = 0.f, p_stex = 0.f;
    float p_nf = 0.f, p_nfb = 0.f, p_lf = 0.f, p_mid = 0.f;
    float p_hf = 0.f, p_syn = 0.f, p_ic = 0.f;

    #pragma unroll
    for (int k = 0; k < (TILE*TILE)/NTHREADS; k++) {
        int p = tid + k * NTHREADS;
        int r = p >> 5, c = p & 31;

        // vertical G3
        float low_i = 0.f, low_p = 0.f, low_m = 0.f;
        #pragma unroll
        for (int t = 0; t < 19; t++) {
            float w = s_g3[t];
            int idx = (r + t)*H3STR + c;
            low_i += w * s_h3[idx];
            low_p += w * s_h3[LOAD*H3STR + idx];
            low_m += w * s_h3[2*LOAD*H3STR + idx];
        }
        // vertical G1
        float g1_i = 0.f, g1_p = 0.f;
        #pragma unroll
        for (int t = 0; t < 7; t++) {
            float w = s_g1[t];
            int idx = (r + t)*H3STR + c;
            g1_i += w * s_h1[idx];
            g1_p += w * s_h1[H1ROWS*H3STR + idx];
        }
        float mid_i = g1_i - low_i;
        float mid_p = g1_p - low_p;

        // 3x3 stencils from raw tiles
        int R = r + R3, C = c + R3;
        int i00 = (R-1)*RSTR + (C-1);
        int i10 = R*RSTR + (C-1);
        int i20 = (R+1)*RSTR + (C-1);

        float a00 = s_xi[i00], a01 = s_xi[i00+1], a02 = s_xi[i00+2];
        float a10 = s_xi[i10], a11 = s_xi[i10+1], a12 = s_xi[i10+2];
        float a20 = s_xi[i20], a21 = s_xi[i20+1], a22 = s_xi[i20+2];
        float gxi = (a02 - a00) + 2.f*(a12 - a10) + (a22 - a20);
        float gyi = (a20 - a00) + 2.f*(a21 - a01) + (a22 - a02);
        float lap_i = a01 + a10 + a12 + a21 - 4.f*a11;

        float b00 = s_yp[i00], b01 = s_yp[i00+1], b02 = s_yp[i00+2];
        float b10 = s_yp[i10], b11 = s_yp[i10+1], b12 = s_yp[i10+2];
        float b20 = s_yp[i20], b21 = s_yp[i20+1], b22 = s_yp[i20+2];
        float gxp = (b02 - b00) + 2.f*(b12 - b10) + (b22 - b20);
        float gyp = (b20 - b00) + 2.f*(b21 - b01) + (b22 - b02);
        float lap_p = b01 + b10 + b12 + b21 - 4.f*b11;

        float xi = a11;
        float yp = b11;

        int g = img + (oy + r)*IMW + (ox + c);
        float wv = wt_g[g];
        float nprd = np_g[g];
        float nsyn = ns_g[g];

        // reconstruction
        p_rc += fabsf(yp * wv - xi * wv);

        // body stats + histograms
        bool body = (xi > 0.15f) & (xi < 0.85f);
        if (body) {
            p_nb += 1.f; p_sxi += xi; p_syp += yp;
            int b1 = (int)(yp * (float)NBINS);
            b1 = min(max(b1, 0), NBINS-1);
            atomicAdd(&s_hist[b1], 1u);
            int b2 = (int)(xi * (float)NBINS);
            b2 = min(max(b2, 0), NBINS-1);
            atomicAdd(&s_hist[NBINS + b2], 1u);
        }

        float gmi = sqrtf(gxi*gxi + gyi*gyi + 1e-8f);
        float gmp = sqrtf(gxp*gxp + gyp*gyp + 1e-8f);

        p_ex += fabsf(gxp - gxi);
        p_ey += fabsf(gyp - gyi);

        bool tex = (gmi > 0.03f) & (gmi < 0.5f);
        if (tex) { p_ntex += 1.f; p_stex += fabsf(gmp - gmi); }

        bool flat = (gmi < 0.03f);
        bool fb = flat & body;
        if (flat) {
            p_nf += 1.f;
            p_hf += fabsf(fabsf(lap_p) - 0.3f * fabsf(lap_i));
            p_ic += fmaxf(gmp - 2.0f * gmi, 0.f);
        }
        if (fb) {
            p_nfb += 1.f;
            p_lf  += fabsf((low_p - low_m) - 0.3f * (low_i - low_m));
            p_mid += fabsf(fabsf(mid_p) - 0.3f * fabsf(mid_i));
            p_syn += fabsf(nprd - nsyn);
        }
    }

    // ---- block reduction of 15 partials ----
    float vals[NACC] = {p_rc, p_nb, p_sxi, p_syp, p_ex, p_ey, p_ntex, p_stex,
                        p_nf, p_nfb, p_lf, p_mid, p_hf, p_syn, p_ic};
    int lane = tid & 31, warp = tid >> 5;
    #pragma unroll
    for (int q = 0; q < NACC; q++) {
        float v = vals[q];
        #pragma unroll
        for (int o = 16; o > 0; o >>= 1) v += __shfl_down_sync(0xffffffffu, v, o);
        if (lane == 0) s_part[q][warp] = v;
    }
    __syncthreads();
    if (tid < NACC) {
        float s = 0.f;
        #pragma unroll
        for (int w = 0; w < 8; w++) s += s_part[tid][w];
        atomicAdd(&g_acc[tid], (double)s);
    }

    // ---- flush histograms ----
    for (int i = tid; i < 2*NBINS; i += NTHREADS) {
        unsigned int h = s_hist[i];
        if (h) atomicAdd(&g_hist[i], h);
    }
}

__device__ double histq(const unsigned int* h, double n, double q) {
    double pos = q * (n - 1.0);
    double cum = 0.0;
    double lastval = 0.0;
    for (int b = 0; b < NBINS; b++) {
        double c = (double)h[b];
        if (c > 0.0) {
            if (pos < cum + c) {
                double frac = (pos - cum + 0.5) / c;
                if (frac < 0.0) frac = 0.0;
                if (frac > 1.0) frac = 1.0;
                return ((double)b + frac) / (double)NBINS;
            }
            lastval = ((double)b + 1.0) / (double)NBINS;
        }
        cum += c;
    }
    return lastval;
}

__global__ void finalize_kernel(float* out) {
    const double n_all = (double)BATCH * IMH * IMW;
    double rc = g_acc[0] / n_all;
    double nb = g_acc[1];
    double denb = fmax(nb, 1.0);
    double mean_in = g_acc[2] / denb;
    double mean_pr = g_acc[3] / denb;
    double q25p = histq(&g_hist[0], nb, 0.25);
    double q75p = histq(&g_hist[0], nb, 0.75);
    double q25i = histq(&g_hist[NBINS], nb, 0.25);
    double q75i = histq(&g_hist[NBINS], nb, 0.75);
    double dm = mean_pr - mean_in;
    double d25 = q25p - q25i, d75 = q75p - q75i;
    double hu = dm*dm + 0.5 * (d25*d25 + d75*d75);
    double loss_hu = (nb > 4096.0) ? hu : 0.0;
    double edge = g_acc[4] / n_all + g_acc[5] / n_all;
    double ntex = g_acc[6];
    double tex = (ntex > 100.0) ? g_acc[7] / fmax(ntex, 1.0) : 0.0;
    double nf = g_acc[8], nfb = g_acc[9];
    double lf  = (nfb > 100.0) ? g_acc[10] / fmax(nfb, 1.0) : 0.0;
    double mid = (nfb > 100.0) ? g_acc[11] / fmax(nfb, 1.0) : 0.0;
    double hf  = (nf  > 100.0) ? g_acc[12] / fmax(nf, 1.0) : 0.0;
    double syn = (nfb > 100.0) ? g_acc[13] / fmax(nfb, 1.0) : 0.0;
    double ic  = (nf  > 100.0) ? g_acc[14] / fmax(nf, 1.0) : 0.0;

    double total = 2.0 * rc + 1.5 * loss_hu + 1.0 * edge + 0.8 * tex
                 + 1.5 * hf + 0.8 * mid + 0.6 * lf + 1.0 * syn + 0.8 * ic;
    out[0] = (float)total;
}

extern "C" void kernel_launch(void* const* d_in, const int* in_sizes, int n_in,
                              void* d_out, int out_size) {
    const float* yp = (const float*)d_in[0];   // y_pred (B,1,1,H,W)
    const float* np = (const float*)d_in[1];   // noise_pred (B,1,1,H,W)
    const float* xi = (const float*)d_in[2];   // x_i
    // d_in[3] = x_ip1 (unused by reference)
    const float* xm = (const float*)d_in[4];   // x_mid
    const float* wt = (const float*)d_in[5];   // W
    const float* ns = (const float*)d_in[6];   // noise_synthetic
    float* out = (float*)d_out;

    cudaFuncSetAttribute(main_kernel,
                         cudaFuncAttributeMaxDynamicSharedMemorySize, SMEM_BYTES);

    zero_kernel<<<16, 256>>>();
    dim3 grid(IMW / TILE, IMH / TILE, BATCH);
    main_kernel<<<grid, NTHREADS, SMEM_BYTES>>>(yp, np, xi, xm, wt, ns);
    finalize_kernel<<<1, 1>>>(out);
}

// round 2
// speedup vs baseline: 4.0240x; 4.0240x over previous
#include <cuda_runtime.h>
#include <math.h>

#define BATCH 16
#define IMH 768
#define IMW 768
#define TILE 32
#define R3 9
#define LOAD 50              // TILE + 18
#define RSTR 53              // odd stride -> no 4-way bank conflicts for 4-wide windows
#define H3STR 33
#define H1ROWS 38
#define NBINS 2048
#define NTHREADS 256
#define NACC 15
#define P3 (LOAD*H3STR)
#define P1 (H1ROWS*H3STR)

#define SMEM_FLOATS (3*LOAD*RSTR + 3*LOAD*H3STR)
#define SMEM_BYTES  (SMEM_FLOATS*4 + 2*NBINS*4)

// Normalized gaussian weights (sigma=3,k=19 and sigma=1,k=7), precomputed.
__device__ constexpr float G3W[19] = {
    0.00147944f, 0.00380430f, 0.00875341f, 0.01802349f, 0.03320783f,
    0.05475024f, 0.08077522f, 0.10663890f, 0.12597909f, 0.13317587f,
    0.12597909f, 0.10663890f, 0.08077522f, 0.05475024f, 0.03320783f,
    0.01802349f, 0.00875341f, 0.00380430f, 0.00147944f };
__device__ constexpr float G1W[7] = {
    0.00443305f, 0.05400558f, 0.24203623f, 0.39905027f,
    0.24203623f, 0.05400558f, 0.00443305f };

__device__ double       g_acc[NACC];     // zero-initialized at load; reset by finalize
__device__ unsigned int g_hist[2*NBINS];

__global__ __launch_bounds__(NTHREADS, 3)
void main_kernel(const float* __restrict__ yp_g,
                 const float* __restrict__ np_g,
                 const float* __restrict__ xi_g,
                 const float* __restrict__ xm_g,
                 const float* __restrict__ wt_g,
                 const float* __restrict__ ns_g)
{
    extern __shared__ float smem[];
    float* s_xi = smem;
    float* s_yp = s_xi + LOAD*RSTR;
    float* s_xm = s_yp + LOAD*RSTR;      // aliased as h1 buffer after G3 h-pass
    float* s_h3 = s_xm + LOAD*RSTR;      // 3 planes of LOAD*H3STR
    unsigned int* s_hist = (unsigned int*)(s_h3 + 3*P3);
    __shared__ float s_part[NACC][8];

    const int tid = threadIdx.x;
    for (int i = tid; i < 2*NBINS; i += NTHREADS) s_hist[i] = 0u;

    const int oy = blockIdx.y * TILE;
    const int ox = blockIdx.x * TILE;
    const int img = blockIdx.z * (IMH * IMW);

    // ---- load raw tiles with halo (zero pad outside image) ----
    for (int i = tid; i < LOAD*LOAD; i += NTHREADS) {
        int r = i / LOAD, c = i - r * LOAD;
        int gy = oy + r - R3, gx = ox + c - R3;
        bool in = ((unsigned)gy < IMH) & ((unsigned)gx < IMW);
        float vx = 0.f, vy = 0.f, vm = 0.f;
        if (in) {
            int g = img + gy * IMW + gx;
            vx = xi_g[g]; vy = yp_g[g]; vm = xm_g[g];
        }
        int o = r*RSTR + c;
        s_xi[o] = vx; s_yp[o] = vy; s_xm[o] = vm;
    }
    __syncthreads();

    // ---- G3 horizontal pass: 50 rows x 8 groups of 4 outputs, sliding window ----
    for (int i = tid; i < LOAD*8; i += NTHREADS) {
        int r = i >> 3, c4 = (i & 7) << 2;
        int base = r*RSTR + c4;
        float a0=0,a1=0,a2=0,a3=0, b0=0,b1=0,b2=0,b3=0, m0=0,m1=0,m2=0,m3=0;
        #pragma unroll
        for (int t = 0; t < 22; t++) {
            float vx = s_xi[base+t], vy = s_yp[base+t], vm = s_xm[base+t];
            if (t <= 18)           { a0 += G3W[t  ]*vx; b0 += G3W[t  ]*vy; m0 += G3W[t  ]*vm; }
            if (t >= 1 && t <= 19) { a1 += G3W[t-1]*vx; b1 += G3W[t-1]*vy; m1 += G3W[t-1]*vm; }
            if (t >= 2 && t <= 20) { a2 += G3W[t-2]*vx; b2 += G3W[t-2]*vy; m2 += G3W[t-2]*vm; }
            if (t >= 3)            { a3 += G3W[t-3]*vx; b3 += G3W[t-3]*vy; m3 += G3W[t-3]*vm; }
        }
        int o = r*H3STR + c4;
        s_h3[o]=a0; s_h3[o+1]=a1; s_h3[o+2]=a2; s_h3[o+3]=a3;
        s_h3[P3+o]=b0; s_h3[P3+o+1]=b1; s_h3[P3+o+2]=b2; s_h3[P3+o+3]=b3;
        s_h3[2*P3+o]=m0; s_h3[2*P3+o+1]=m1; s_h3[2*P3+o+2]=m2; s_h3[2*P3+o+3]=m3;
    }
    __syncthreads();

    // ---- G1 horizontal pass into aliased s_xm (raw x_mid no longer needed) ----
    float* s_h1 = s_xm;
    for (int i = tid; i < H1ROWS*8; i += NTHREADS) {
        int r = i >> 3, c4 = (i & 7) << 2;
        int base = (r + 6)*RSTR + c4 + 6;
        float a0=0,a1=0,a2=0,a3=0, b0=0,b1=0,b2=0,b3=0;
        #pragma unroll
        for (int t = 0; t < 10; t++) {
            float vx = s_xi[base+t], vy = s_yp[base+t];
            if (t <= 6)           { a0 += G1W[t  ]*vx; b0 += G1W[t  ]*vy; }
            if (t >= 1 && t <= 7) { a1 += G1W[t-1]*vx; b1 += G1W[t-1]*vy; }
            if (t >= 2 && t <= 8) { a2 += G1W[t-2]*vx; b2 += G1W[t-2]*vy; }
            if (t >= 3)           { a3 += G1W[t-3]*vx; b3 += G1W[t-3]*vy; }
        }
        int o = r*H3STR + c4;
        s_h1[o]=a0; s_h1[o+1]=a1; s_h1[o+2]=a2; s_h1[o+3]=a3;
        s_h1[P1+o]=b0; s_h1[P1+o+1]=b1; s_h1[P1+o+2]=b2; s_h1[P1+o+3]=b3;
    }
    __syncthreads();

    // ---- per-pixel phase: thread owns column c, 4 consecutive rows r0..r0+3 ----
    const int c  = tid & 31;
    const int r0 = (tid >> 5) << 2;

    // vertical G3 (sliding window over 22 rows)
    float LI[4] = {0,0,0,0}, LP[4] = {0,0,0,0}, LM[4] = {0,0,0,0};
    #pragma unroll
    for (int t = 0; t < 22; t++) {
        int idx = (r0 + t)*H3STR + c;
        float vx = s_h3[idx], vy = s_h3[P3+idx], vm = s_h3[2*P3+idx];
        if (t <= 18)           { LI[0]+=G3W[t  ]*vx; LP[0]+=G3W[t  ]*vy; LM[0]+=G3W[t  ]*vm; }
        if (t >= 1 && t <= 19) { LI[1]+=G3W[t-1]*vx; LP[1]+=G3W[t-1]*vy; LM[1]+=G3W[t-1]*vm; }
        if (t >= 2 && t <= 20) { LI[2]+=G3W[t-2]*vx; LP[2]+=G3W[t-2]*vy; LM[2]+=G3W[t-2]*vm; }
        if (t >= 3)            { LI[3]+=G3W[t-3]*vx; LP[3]+=G3W[t-3]*vy; LM[3]+=G3W[t-3]*vm; }
    }
    // vertical G1 (window over 10 rows)
    float GI[4] = {0,0,0,0}, GP[4] = {0,0,0,0};
    #pragma unroll
    for (int t = 0; t < 10; t++) {
        int idx = (r0 + t)*H3STR + c;
        float vx = s_h1[idx], vy = s_h1[P1+idx];
        if (t <= 6)           { GI[0]+=G1W[t  ]*vx; GP[0]+=G1W[t  ]*vy; }
        if (t >= 1 && t <= 7) { GI[1]+=G1W[t-1]*vx; GP[1]+=G1W[t-1]*vy; }
        if (t >= 2 && t <= 8) { GI[2]+=G1W[t-2]*vx; GP[2]+=G1W[t-2]*vy; }
        if (t >= 3)           { GI[3]+=G1W[t-3]*vx; GP[3]+=G1W[t-3]*vy; }
    }

    float p_rc=0,p_nb=0,p_sxi=0,p_syp=0,p_ex=0,p_ey=0,p_ntex=0,p_stex=0;
    float p_nf=0,p_nfb=0,p_lf=0,p_mid=0,p_hf=0,p_syn=0,p_ic=0;

    // rolling 3x3 stencil window over rows r0-1 .. r0+4
    int rb = (r0 + R3 - 1)*RSTR + (c + R3 - 1);
    float x00=s_xi[rb],      x01=s_xi[rb+1],      x02=s_xi[rb+2];
    float y00=s_yp[rb],      y01=s_yp[rb+1],      y02=s_yp[rb+2];
    float x10=s_xi[rb+RSTR], x11=s_xi[rb+RSTR+1], x12=s_xi[rb+RSTR+2];
    float y10=s_yp[rb+RSTR], y11=s_yp[rb+RSTR+1], y12=s_yp[rb+RSTR+2];

    #pragma unroll
    for (int j = 0; j < 4; j++) {
        int rbn = rb + (j+2)*RSTR;
        float x20=s_xi[rbn], x21=s_xi[rbn+1], x22=s_xi[rbn+2];
        float y20=s_yp[rbn], y21=s_yp[rbn+1], y22=s_yp[rbn+2];

        float gxi = (x02 - x00) + 2.f*(x12 - x10) + (x22 - x20);
        float gyi = (x20 - x00) + 2.f*(x21 - x01) + (x22 - x02);
        float lap_i = x01 + x10 + x12 + x21 - 4.f*x11;
        float gxp = (y02 - y00) + 2.f*(y12 - y10) + (y22 - y20);
        float gyp = (y20 - y00) + 2.f*(y21 - y01) + (y22 - y02);
        float lap_p = y01 + y10 + y12 + y21 - 4.f*y11;

        float xi = x11, yp = y11;

        int g = img + (oy + r0 + j)*IMW + (ox + c);
        float wv   = wt_g[g];
        float nprd = np_g[g];
        float nsyn = ns_g[g];

        p_rc += fabsf(yp*wv - xi*wv);

        bool body = (xi > 0.15f) & (xi < 0.85f);
        if (body) {
            p_nb += 1.f; p_sxi += xi; p_syp += yp;
            int b1 = min(max((int)(yp * (float)NBINS), 0), NBINS-1);
            atomicAdd(&s_hist[b1], 1u);
            int b2 = min(max((int)(xi * (float)NBINS), 0), NBINS-1);
            atomicAdd(&s_hist[NBINS + b2], 1u);
        }

        float gmi = sqrtf(gxi*gxi + gyi*gyi + 1e-8f);
        float gmp = sqrtf(gxp*gxp + gyp*gyp + 1e-8f);

        p_ex += fabsf(gxp - gxi);
        p_ey += fabsf(gyp - gyi);

        bool tex = (gmi > 0.03f) & (gmi < 0.5f);
        if (tex) { p_ntex += 1.f; p_stex += fabsf(gmp - gmi); }

        bool flat = (gmi < 0.03f);
        if (flat) {
            p_nf += 1.f;
            p_hf += fabsf(fabsf(lap_p) - 0.3f*fabsf(lap_i));
            p_ic += fmaxf(gmp - 2.0f*gmi, 0.f);
            if (body) {
                p_nfb += 1.f;
                p_lf  += fabsf((LP[j] - LM[j]) - 0.3f*(LI[j] - LM[j]));
                float mid_i = GI[j] - LI[j];
                float mid_p = GP[j] - LP[j];
                p_mid += fabsf(fabsf(mid_p) - 0.3f*fabsf(mid_i));
                p_syn += fabsf(nprd - nsyn);
            }
        }

        x00=x10; x01=x11; x02=x12; x10=x20; x11=x21; x12=x22;
        y00=y10; y01=y11; y02=y12; y10=y20; y11=y21; y12=y22;
    }

    // ---- block reduction of 15 partials ----
    float vals[NACC] = {p_rc, p_nb, p_sxi, p_syp, p_ex, p_ey, p_ntex, p_stex,
                        p_nf, p_nfb, p_lf, p_mid, p_hf, p_syn, p_ic};
    int lane = tid & 31, warp = tid >> 5;
    #pragma unroll
    for (int q = 0; q < NACC; q++) {
        float v = vals[q];
        #pragma unroll
        for (int o = 16; o > 0; o >>= 1) v += __shfl_down_sync(0xffffffffu, v, o);
        if (lane == 0) s_part[q][warp] = v;
    }
    __syncthreads();
    if (tid < NACC) {
        float s = 0.f;
        #pragma unroll
        for (int w = 0; w < 8; w++) s += s_part[tid][w];
        atomicAdd(&g_acc[tid], (double)s);
    }

    for (int i = tid; i < 2*NBINS; i += NTHREADS) {
        unsigned int h = s_hist[i];
        if (h) atomicAdd(&g_hist[i], h);
    }
}

__global__ __launch_bounds__(256)
void finalize_kernel(float* out) {
    __shared__ unsigned int s_cum[NBINS];
    __shared__ unsigned int s_wtot[8];
    __shared__ double s_q[4];

    const int tid = threadIdx.x, lane = tid & 31, warp = tid >> 5;
    const double nb = g_acc[1];

    for (int h = 0; h < 2; h++) {
        unsigned int loc[8];
        unsigned int run = 0;
        #pragma unroll
        for (int k = 0; k < 8; k++) { run += g_hist[h*NBINS + tid*8 + k]; loc[k] = run; }
        unsigned int v = run;
        #pragma unroll
        for (int o = 1; o < 32; o <<= 1) {
            unsigned int u = __shfl_up_sync(0xffffffffu, v, o);
            if (lane >= o) v += u;
        }
        if (lane == 31) s_wtot[warp] = v;
        __syncthreads();
        unsigned int woff = 0;
        for (int w = 0; w < warp; w++) woff += s_wtot[w];
        unsigned int off = woff + v - run;   // exclusive prefix for this chunk
        #pragma unroll
        for (int k = 0; k < 8; k++) s_cum[tid*8 + k] = loc[k] + off;
        __syncthreads();
        if (tid < 2) {
            double q = (tid == 0) ? 0.25 : 0.75;
            double pos = q * (nb - 1.0);
            int lo = 0, hi = NBINS - 1;
            while (lo < hi) {
                int m = (lo + hi) >> 1;
                if ((double)s_cum[m] > pos) hi = m; else lo = m + 1;
            }
            int b = lo;
            unsigned int cb = s_cum[b];
            unsigned int pv = b ? s_cum[b-1] : 0u;
            double cnt = (double)(cb - pv);
            double val = 0.0;
            if (cnt > 0.0) {
                double frac = (pos - (double)pv + 0.5) / cnt;
                frac = fmin(fmax(frac, 0.0), 1.0);
                val = ((double)b + frac) / (double)NBINS;
            }
            s_q[h*2 + tid] = val;
        }
        __syncthreads();
    }

    if (tid == 0) {
        const double n_all = (double)BATCH * IMH * IMW;
        double rc = g_acc[0] / n_all;
        double denb = fmax(nb, 1.0);
        double mean_in = g_acc[2] / denb;
        double mean_pr = g_acc[3] / denb;
        double dm  = mean_pr - mean_in;
        double d25 = s_q[0] - s_q[2];
        double d75 = s_q[1] - s_q[3];
        double hu  = dm*dm + 0.5*(d25*d25 + d75*d75);
        double loss_hu = (nb > 4096.0) ? hu : 0.0;
        double edge = g_acc[4]/n_all + g_acc[5]/n_all;
        double ntex = g_acc[6];
        double tex = (ntex > 100.0) ? g_acc[7]/fmax(ntex, 1.0) : 0.0;
        double nf = g_acc[8], nfb = g_acc[9];
        double lf  = (nfb > 100.0) ? g_acc[10]/fmax(nfb, 1.0) : 0.0;
        double mid = (nfb > 100.0) ? g_acc[11]/fmax(nfb, 1.0) : 0.0;
        double hf  = (nf  > 100.0) ? g_acc[12]/fmax(nf, 1.0)  : 0.0;
        double syn = (nfb > 100.0) ? g_acc[13]/fmax(nfb, 1.0) : 0.0;
        double ic  = (nf  > 100.0) ? g_acc[14]/fmax(nf, 1.0)  : 0.0;

        double total = 2.0*rc + 1.5*loss_hu + 1.0*edge + 0.8*tex
                     + 1.5*hf + 0.8*mid + 0.6*lf + 1.0*syn + 0.8*ic;
        out[0] = (float)total;
    }
    __syncthreads();

    // reset global state for the next (deterministic) invocation
    for (int i = tid; i < 2*NBINS; i += 256) g_hist[i] = 0u;
    if (tid < NACC) g_acc[tid] = 0.0;
}

extern "C" void kernel_launch(void* const* d_in, const int* in_sizes, int n_in,
                              void* d_out, int out_size) {
    const float* yp = (const float*)d_in[0];   // y_pred
    const float* np = (const float*)d_in[1];   // noise_pred
    const float* xi = (const float*)d_in[2];   // x_i
    // d_in[3] = x_ip1 (unused by reference)
    const float* xm = (const float*)d_in[4];   // x_mid
    const float* wt = (const float*)d_in[5];   // W
    const float* ns = (const float*)d_in[6];   // noise_synthetic
    float* out = (float*)d_out;

    cudaFuncSetAttribute(main_kernel,
                         cudaFuncAttributeMaxDynamicSharedMemorySize, SMEM_BYTES);

    dim3 grid(IMW / TILE, IMH / TILE, BATCH);
    main_kernel<<<grid, NTHREADS, SMEM_BYTES>>>(yp, np, xi, xm, wt, ns);
    finalize_kernel<<<1, 256>>>(out);
}